// round 8
// baseline (speedup 1.0000x reference)
#include <cuda_runtime.h>
#include <cuda_fp16.h>
#include <cstdint>

#define B 16
#define S 2048
#define D 128
#define QT 128
#define NTILES 16
#define THREADS 256
#define PADT 136                 // padded row stride (fp16 elems) -> conflict-free LDS/LDSM
#define TB 34816                 // bytes per 128x128 padded fp16 tile (128*PADT*2)

// ---------------- device scratch (no allocation allowed) ----------------
__device__ __half g_Kh[B * S * D];
__device__ __half g_Vh[B * S * D], g_Vl[B * S * D];   // V in natural [b][s][d] layout
__device__ float g_L[B * S];

// ---------------- PTX helpers (baseline sm_80-level features only) ----------------
__device__ __forceinline__ uint32_t smem_u32(const void* p) {
    uint32_t a;
    asm("{ .reg .u64 t; cvta.to.shared.u64 t, %1; cvt.u32.u64 %0, t; }" : "=r"(a) : "l"(p));
    return a;
}
__device__ __forceinline__ void ldsm4(uint32_t r[4], uint32_t a) {
    asm volatile("ldmatrix.sync.aligned.m8n8.x4.shared.b16 {%0,%1,%2,%3}, [%4];"
                 : "=r"(r[0]), "=r"(r[1]), "=r"(r[2]), "=r"(r[3]) : "r"(a));
}
__device__ __forceinline__ void ldsm4t(uint32_t r[4], uint32_t a) {
    asm volatile("ldmatrix.sync.aligned.m8n8.x4.trans.shared.b16 {%0,%1,%2,%3}, [%4];"
                 : "=r"(r[0]), "=r"(r[1]), "=r"(r[2]), "=r"(r[3]) : "r"(a));
}
__device__ __forceinline__ void mma16816(float c[4], const uint32_t a[4],
                                         uint32_t b0, uint32_t b1) {
    asm("mma.sync.aligned.m16n8k16.row.col.f32.f16.f16.f32 "
        "{%0,%1,%2,%3},{%4,%5,%6,%7},{%8,%9},{%0,%1,%2,%3};"
        : "+f"(c[0]), "+f"(c[1]), "+f"(c[2]), "+f"(c[3])
        : "r"(a[0]), "r"(a[1]), "r"(a[2]), "r"(a[3]), "r"(b0), "r"(b1));
}
__device__ __forceinline__ void cp16(uint32_t s, const void* g) {
    asm volatile("cp.async.cg.shared.global [%0], [%1], 16;" :: "r"(s), "l"(g) : "memory");
}
#define CP_COMMIT()  asm volatile("cp.async.commit_group;" ::: "memory")
#define CP_WAIT(n)   asm volatile("cp.async.wait_group %0;" :: "n"(n) : "memory")

// per-lane ldmatrix.x4 base for a 16x16 frag at (row0, col0): non-trans (A / K-major B)
__device__ __forceinline__ uint32_t lmaddr(uint32_t base, int row0, int col0, int lane) {
    int r = lane & 7, which = lane >> 3;
    int row = row0 + ((which & 1) << 3) + r;
    int col = col0 + ((which >> 1) << 3);
    return base + (uint32_t)(row * PADT + col) * 2u;
}
// per-lane ldmatrix.x4.trans base for V[s][d]: quadrants (k-half, n-half)
__device__ __forceinline__ uint32_t lmaddrT(uint32_t base, int col0, int lane) {
    int row = (lane & 7) + 8 * ((lane >> 3) & 1);    // k (=s) offset
    int col = col0 + 8 * (lane >> 4);                // n (=d) offset
    return base + (uint32_t)(row * PADT + col) * 2u;
}

// cooperative async 128x128 fp16 tile copy: gmem(row stride rs) -> padded smem
__device__ __forceinline__ void loadTileAsync(uint32_t sdst, const __half* __restrict__ src,
                                              int rs, int tid) {
    #pragma unroll
    for (int i = 0; i < 8; i++) {
        int idx = tid + i * THREADS;       // 2048 16B chunks
        int row = idx >> 4;
        int c   = (idx & 15) * 8;
        cp16(sdst + (uint32_t)(row * PADT + c) * 2u, src + (size_t)row * rs + c);
    }
}

// ---------------- pre-kernel: K -> fp16 hi ; V -> fp16 hi+lo (same layout) ----------------
__global__ __launch_bounds__(256) void prep_kernel(const float* __restrict__ k,
                                                   const float* __restrict__ v) {
    size_t i = ((size_t)blockIdx.x * 256 + threadIdx.x) * 4;
    if (blockIdx.y == 0) {
        float4 x = *(const float4*)(k + i);
        __half2 a = __floats2half2_rn(x.x, x.y);
        __half2 b2 = __floats2half2_rn(x.z, x.w);
        *(uint2*)(g_Kh + i) = make_uint2(*(uint32_t*)&a, *(uint32_t*)&b2);
    } else {
        float4 x = *(const float4*)(v + i);
        __half h0 = __float2half_rn(x.x), h1 = __float2half_rn(x.y);
        __half h2 = __float2half_rn(x.z), h3 = __float2half_rn(x.w);
        __half l0 = __float2half_rn(x.x - __half2float(h0));
        __half l1 = __float2half_rn(x.y - __half2float(h1));
        __half l2 = __float2half_rn(x.z - __half2float(h2));
        __half l3 = __float2half_rn(x.w - __half2float(h3));
        __half2 ha = {h0, h1}, hb = {h2, h3}, la = {l0, l1}, lb = {l2, l3};
        *(uint2*)(g_Vh + i) = make_uint2(*(uint32_t*)&ha, *(uint32_t*)&hb);
        *(uint2*)(g_Vl + i) = make_uint2(*(uint32_t*)&la, *(uint32_t*)&lb);
    }
}

// ---------------- main attention kernel ----------------
// smem (byte offsets): [Q:0][K0:TB][K1:2TB][Vh:3TB][Vl:4TB][P:5TB]  total 6*TB = 208896
__global__ __launch_bounds__(THREADS, 1) void attn_mma_kernel(const float* __restrict__ q,
                                                              float* __restrict__ ctx,
                                                              float* __restrict__ attn) {
    extern __shared__ char smraw[];
    uint32_t sb = smem_u32(smraw);
    const uint32_t sQ = sb, sK0 = sb + TB, sK1 = sb + 2 * TB;
    const uint32_t sVh = sb + 3 * TB, sVl = sb + 4 * TB, sP = sb + 5 * TB;
    __half* Qt = (__half*)smraw;
    __half* Ps = (__half*)(smraw + 5 * TB);

    const int tid  = threadIdx.x;
    const int w    = tid >> 5, lane = tid & 31;
    const int wm   = w & 3, wn = w >> 2;       // warp tile: rows 32*wm, keys/cols 64*wn
    const int g    = lane >> 2, tib = lane & 3;
    const int b    = blockIdx.y, qt = blockIdx.x;

    // ---- prologue: stage Q (fp32, contiguous 64KB) into V buffers + load K(0) ----
    const size_t qoff = ((size_t)b * S + (size_t)qt * QT) * D;
    #pragma unroll
    for (int i = 0; i < 16; i++) {
        int idx = tid + i * THREADS;
        cp16(sVh + (uint32_t)idx * 16u, q + qoff + (size_t)idx * 4);
    }
    loadTileAsync(sK0, g_Kh + (size_t)b * S * D, D, tid);
    CP_COMMIT();
    CP_WAIT(0);
    __syncthreads();
    {   // convert Q fp32 -> fp16 into padded Q tile
        const float4* stage = (const float4*)(smraw + 3 * TB);
        #pragma unroll
        for (int i = 0; i < 16; i++) {
            int idx = tid + i * THREADS;
            int row = idx >> 5, c4 = (idx & 31) * 4;
            float4 x = stage[idx];
            __half2 a = __floats2half2_rn(x.x, x.y);
            __half2 b2 = __floats2half2_rn(x.z, x.w);
            *(uint2*)(Qt + row * PADT + c4) = make_uint2(*(uint32_t*)&a, *(uint32_t*)&b2);
        }
    }
    __syncthreads();   // Q visible; V staging free

    // per-lane ldmatrix bases
    const uint32_t aQ0 = lmaddr(sQ, 32 * wm, 0, lane);
    const uint32_t aQ1 = lmaddr(sQ, 32 * wm + 16, 0, lane);
    const uint32_t aK0 = lmaddr(sK0, 64 * wn, 0, lane);
    const uint32_t aK1 = lmaddr(sK1, 64 * wn, 0, lane);
    const uint32_t aVhB = lmaddrT(sVh, 64 * wn, lane);
    const uint32_t aVlB = lmaddrT(sVl, 64 * wn, lane);
    const uint32_t aP0 = lmaddr(sP, 32 * wm, 0, lane);
    const uint32_t aP1 = lmaddr(sP, 32 * wm + 16, 0, lane);

    float O[2][8][4] = {};
    float Ls[4] = {0.f, 0.f, 0.f, 0.f};
    uint32_t pha[2][8], phb[2][8];
    const float SC = 0.08838834764831843f;   // 1/sqrt(128)

    #pragma unroll 1
    for (int kt = 0; kt < NTILES; kt++) {
        CP_WAIT(0);            // K(kt) landed (this thread's chunks)
        __syncthreads();       // K visible; all warps past PV(kt-1) (V,P free)

        // prefetch V(kt) — overlaps QK
        {
            const size_t voff = ((size_t)b * S + (size_t)kt * 128) * D;
            loadTileAsync(sVh, g_Vh + voff, D, tid);
            loadTileAsync(sVl, g_Vl + voff, D, tid);
        }
        CP_COMMIT();
        // prefetch K(kt+1) into the other buffer — overlaps QK/exp/PV
        if (kt + 1 < NTILES) {
            const size_t koff = ((size_t)b * S + (size_t)(kt + 1) * 128) * D;
            loadTileAsync((kt & 1) ? sK0 : sK1, g_Kh + koff, D, tid);
        }
        CP_COMMIT();

        // ---- QK^T: single-term fp16 (Qh*Kh), fp32 accum ----
        float Cr[2][8][4] = {};
        const uint32_t aK = (kt & 1) ? aK1 : aK0;
        #pragma unroll
        for (int kst = 0; kst < 8; kst++) {
            const uint32_t cofs = kst * 32u;
            uint32_t q0[4], q1[4];
            ldsm4(q0, aQ0 + cofs);
            ldsm4(q1, aQ1 + cofs);
            #pragma unroll
            for (int np = 0; np < 4; np++) {
                const uint32_t rofs = (uint32_t)(np * 16 * PADT) * 2u + cofs;
                uint32_t kh4[4];
                ldsm4(kh4, aK + rofs);
                mma16816(Cr[0][2 * np],     q0, kh4[0], kh4[2]);
                mma16816(Cr[0][2 * np + 1], q0, kh4[1], kh4[3]);
                mma16816(Cr[1][2 * np],     q1, kh4[0], kh4[2]);
                mma16816(Cr[1][2 * np + 1], q1, kh4[1], kh4[3]);
            }
        }

        // ---- exp, unnormalized attn out, P pack (regs + smem for partners) ----
        #pragma unroll
        for (int mt = 0; mt < 2; mt++) {
            const int lrow = 32 * wm + 16 * mt + g;
            float* arow = attn + ((size_t)(b * S + qt * QT + lrow)) * S
                        + kt * 128 + 64 * wn + 2 * tib;
            #pragma unroll
            for (int n = 0; n < 8; n++) {
                float p0 = __expf(Cr[mt][n][0] * SC);
                float p1 = __expf(Cr[mt][n][1] * SC);
                float p2 = __expf(Cr[mt][n][2] * SC);
                float p3 = __expf(Cr[mt][n][3] * SC);
                Ls[2 * mt]     += p0 + p1;
                Ls[2 * mt + 1] += p2 + p3;
                *(float2*)(arow + 8 * n)                 = make_float2(p0, p1);
                *(float2*)(arow + 8 * (size_t)S + 8 * n) = make_float2(p2, p3);
                __half2 h0 = __floats2half2_rn(p0, p1);
                __half2 h1 = __floats2half2_rn(p2, p3);
                uint32_t u0 = *(uint32_t*)&h0, u1 = *(uint32_t*)&h1;
                pha[mt][n] = u0;
                phb[mt][n] = u1;
                const int col = 64 * wn + 8 * n + 2 * tib;
                *(uint32_t*)(Ps + lrow * PADT + col)       = u0;
                *(uint32_t*)(Ps + (lrow + 8) * PADT + col) = u1;
            }
        }

        if (kt == NTILES - 1) { CP_WAIT(0); } else { CP_WAIT(1); }   // V(kt) landed
        __syncthreads();       // V + P visible to all warps

        // ---- PV: O += P * V  (2-term: Ph*Vh + Ph*Vl), V B-frags via ldmatrix.trans ----
        #pragma unroll
        for (int kst = 0; kst < 8; kst++) {
            const uint32_t cofs = kst * 32u;
            uint32_t a0[4], a1[4];
            if ((kst >> 2) == wn) {        // own keys: P frags already in registers
                const int j = kst & 3;
                a0[0] = pha[0][2 * j]; a0[1] = phb[0][2 * j];
                a0[2] = pha[0][2 * j + 1]; a0[3] = phb[0][2 * j + 1];
                a1[0] = pha[1][2 * j]; a1[1] = phb[1][2 * j];
                a1[2] = pha[1][2 * j + 1]; a1[3] = phb[1][2 * j + 1];
            } else {
                ldsm4(a0, aP0 + cofs);
                ldsm4(a1, aP1 + cofs);
            }
            #pragma unroll
            for (int np = 0; np < 4; np++) {
                const uint32_t vofs = (uint32_t)(16 * kst * PADT + 16 * np) * 2u;
                uint32_t vh4[4], vl4[4];
                ldsm4t(vh4, aVhB + vofs);
                ldsm4t(vl4, aVlB + vofs);
                // trans quadrants: (r0,r1) = n-block0 (k0-7,k8-15), (r2,r3) = n-block1
                mma16816(O[0][2 * np],     a0, vh4[0], vh4[1]);
                mma16816(O[0][2 * np],     a0, vl4[0], vl4[1]);
                mma16816(O[0][2 * np + 1], a0, vh4[2], vh4[3]);
                mma16816(O[0][2 * np + 1], a0, vl4[2], vl4[3]);
                mma16816(O[1][2 * np],     a1, vh4[0], vh4[1]);
                mma16816(O[1][2 * np],     a1, vl4[0], vl4[1]);
                mma16816(O[1][2 * np + 1], a1, vh4[2], vh4[3]);
                mma16816(O[1][2 * np + 1], a1, vl4[2], vl4[3]);
            }
        }
    }

    // ---- L reduction: quad shfl + cross-wn via smem (reuse P space) ----
    __syncthreads();
    float* LR = (float*)Ps;
    #pragma unroll
    for (int i = 0; i < 4; i++) {
        float l = Ls[i];
        l += __shfl_xor_sync(0xffffffffu, l, 1);
        l += __shfl_xor_sync(0xffffffffu, l, 2);
        Ls[i] = l;
    }
    if (tib == 0) {
        #pragma unroll
        for (int mt = 0; mt < 2; mt++) {
            LR[wn * 128 + 32 * wm + 16 * mt + g]     = Ls[2 * mt];
            LR[wn * 128 + 32 * wm + 16 * mt + g + 8] = Ls[2 * mt + 1];
        }
    }
    __syncthreads();

    float inv[2][2];
    #pragma unroll
    for (int mt = 0; mt < 2; mt++) {
        int r0 = 32 * wm + 16 * mt + g;
        float L0 = LR[r0] + LR[128 + r0];
        float L1 = LR[r0 + 8] + LR[128 + r0 + 8];
        inv[mt][0] = 1.0f / L0;
        inv[mt][1] = 1.0f / L1;
        if (wn == 0 && tib == 0) {
            g_L[(size_t)b * S + qt * QT + r0]     = L0;
            g_L[(size_t)b * S + qt * QT + r0 + 8] = L1;
        }
    }

    // ---- normalized context store ----
    #pragma unroll
    for (int mt = 0; mt < 2; mt++) {
        const int lrow = 32 * wm + 16 * mt + g;
        float* cp = ctx + ((size_t)(b * S + qt * QT + lrow)) * D + 64 * wn + 2 * tib;
        #pragma unroll
        for (int n = 0; n < 8; n++) {
            *(float2*)(cp + 8 * n)         = make_float2(O[mt][n][0] * inv[mt][0],
                                                         O[mt][n][1] * inv[mt][0]);
            *(float2*)(cp + 8 * D + 8 * n) = make_float2(O[mt][n][2] * inv[mt][1],
                                                         O[mt][n][3] * inv[mt][1]);
        }
    }
}

// normalize attn in place: 8 float4 per thread, all one row (amortized g_L, MLP=8)
__global__ __launch_bounds__(256) void attn_norm_kernel(float* __restrict__ attn) {
    int idx = blockIdx.x * 256 + threadIdx.x;
    int row = idx >> 6;                      // 64 threads per row (512 float4/row)
    int c   = (idx & 63) * 8;
    float inv = 1.0f / g_L[row];
    float4* a = (float4*)(attn + (size_t)row * S) + c;
    #pragma unroll
    for (int j = 0; j < 8; j++) {
        float4 t = a[j];
        t.x *= inv; t.y *= inv; t.z *= inv; t.w *= inv;
        a[j] = t;
    }
}

// ---------------- launch ----------------
extern "C" void kernel_launch(void* const* d_in, const int* in_sizes, int n_in,
                              void* d_out, int out_size) {
    const float* q = (const float*)d_in[0];
    const float* k = (const float*)d_in[1];
    const float* v = (const float*)d_in[2];
    float* ctx  = (float*)d_out;                       // [B,S,D]
    float* attn = (float*)d_out + (size_t)B * S * D;   // [B,S,S]

    const int smem_bytes = 6 * TB;                     // 208,896 B
    cudaFuncSetAttribute(attn_mma_kernel,
                         cudaFuncAttributeMaxDynamicSharedMemorySize, smem_bytes);

    prep_kernel<<<dim3((B * S * D / 4) / 256, 2), 256>>>(k, v);
    attn_mma_kernel<<<dim3(S / QT, B), THREADS, smem_bytes>>>(q, ctx, attn);
    attn_norm_kernel<<<(B * S * 64) / 256, 256>>>(attn);
}

// round 9
// speedup vs baseline: 1.1453x; 1.1453x over previous
#include <cuda_runtime.h>
#include <cuda_fp16.h>
#include <cstdint>

#define B 16
#define S 2048
#define D 128
#define QT 128
#define KT 64
#define NTILES (S / KT)          // 32
#define THREADS 256
#define PADT 136                 // stride (fp16) for 128-col tiles -> conflict-free LDSM
#define PADP 72                  // stride (fp16) for 64-col P tile -> conflict-free LDSM
#define TBQ (128 * PADT * 2)     // 34816 B  (Q tile)
#define TBK (KT * PADT * 2)      // 17408 B  (K / V tiles)
#define TBP (128 * PADP * 2)     // 18432 B  (P tile)
#define SMEM_TOTAL (TBQ + 3 * TBK + TBP)   // 105472 B -> 2 CTAs/SM

// ---------------- device scratch (no allocation allowed) ----------------
__device__ __half g_Kh[B * S * D];
__device__ __half g_Vh[B * S * D];
__device__ float g_L[B * S];

// ---------------- PTX helpers (baseline sm_80-level features only) ----------------
__device__ __forceinline__ uint32_t smem_u32(const void* p) {
    uint32_t a;
    asm("{ .reg .u64 t; cvta.to.shared.u64 t, %1; cvt.u32.u64 %0, t; }" : "=r"(a) : "l"(p));
    return a;
}
__device__ __forceinline__ void ldsm4(uint32_t r[4], uint32_t a) {
    asm volatile("ldmatrix.sync.aligned.m8n8.x4.shared.b16 {%0,%1,%2,%3}, [%4];"
                 : "=r"(r[0]), "=r"(r[1]), "=r"(r[2]), "=r"(r[3]) : "r"(a));
}
__device__ __forceinline__ void ldsm4t(uint32_t r[4], uint32_t a) {
    asm volatile("ldmatrix.sync.aligned.m8n8.x4.trans.shared.b16 {%0,%1,%2,%3}, [%4];"
                 : "=r"(r[0]), "=r"(r[1]), "=r"(r[2]), "=r"(r[3]) : "r"(a));
}
__device__ __forceinline__ void mma16816(float c[4], const uint32_t a[4],
                                         uint32_t b0, uint32_t b1) {
    asm("mma.sync.aligned.m16n8k16.row.col.f32.f16.f16.f32 "
        "{%0,%1,%2,%3},{%4,%5,%6,%7},{%8,%9},{%0,%1,%2,%3};"
        : "+f"(c[0]), "+f"(c[1]), "+f"(c[2]), "+f"(c[3])
        : "r"(a[0]), "r"(a[1]), "r"(a[2]), "r"(a[3]), "r"(b0), "r"(b1));
}
__device__ __forceinline__ void cp16(uint32_t s, const void* g) {
    asm volatile("cp.async.cg.shared.global [%0], [%1], 16;" :: "r"(s), "l"(g) : "memory");
}
#define CP_COMMIT()  asm volatile("cp.async.commit_group;" ::: "memory")
#define CP_WAIT(n)   asm volatile("cp.async.wait_group %0;" :: "n"(n) : "memory")

// per-lane ldmatrix.x4 base (non-trans) at (row0,col0), given row stride in elems
__device__ __forceinline__ uint32_t lmaddr(uint32_t base, int row0, int col0,
                                           int lane, int stride) {
    int r = lane & 7, which = lane >> 3;
    int row = row0 + ((which & 1) << 3) + r;
    int col = col0 + ((which >> 1) << 3);
    return base + (uint32_t)(row * stride + col) * 2u;
}
// per-lane ldmatrix.x4.trans base for V[s][d] tiles (stride PADT)
__device__ __forceinline__ uint32_t lmaddrT(uint32_t base, int col0, int lane) {
    int row = (lane & 7) + 8 * ((lane >> 3) & 1);    // key offset
    int col = col0 + 8 * (lane >> 4);                // d offset
    return base + (uint32_t)(row * PADT + col) * 2u;
}

// cooperative async 64x128 fp16 tile copy: gmem(D stride) -> padded smem
__device__ __forceinline__ void loadTile64(uint32_t sdst, const __half* __restrict__ src,
                                           int tid) {
    #pragma unroll
    for (int i = 0; i < 4; i++) {
        int idx = tid + i * THREADS;       // 1024 16B chunks
        int row = idx >> 4;
        int c   = (idx & 15) * 8;
        cp16(sdst + (uint32_t)(row * PADT + c) * 2u, src + (size_t)row * D + c);
    }
}

// ---------------- pre-kernel: K,V -> fp16 ----------------
__global__ __launch_bounds__(256) void prep_kernel(const float* __restrict__ k,
                                                   const float* __restrict__ v) {
    size_t i = ((size_t)blockIdx.x * 256 + threadIdx.x) * 4;
    const float* src = (blockIdx.y == 0) ? k : v;
    __half* dst = (blockIdx.y == 0) ? g_Kh : g_Vh;
    float4 x = *(const float4*)(src + i);
    __half2 a = __floats2half2_rn(x.x, x.y);
    __half2 b2 = __floats2half2_rn(x.z, x.w);
    *(uint2*)(dst + i) = make_uint2(*(uint32_t*)&a, *(uint32_t*)&b2);
}

// ---------------- main attention kernel ----------------
// smem: [Q:0][K0:TBQ][K1:+TBK][V:+TBK][P:+TBK]
__global__ __launch_bounds__(THREADS, 2) void attn_mma_kernel(const float* __restrict__ q,
                                                              float* __restrict__ ctx,
                                                              float* __restrict__ attn) {
    extern __shared__ char smraw[];
    uint32_t sb = smem_u32(smraw);
    const uint32_t sQ = sb, sK0 = sb + TBQ, sK1 = sK0 + TBK;
    const uint32_t sV = sK1 + TBK, sP = sV + TBK;
    __half* Qt = (__half*)smraw;
    __half* Ps = (__half*)(smraw + TBQ + 3 * TBK);

    const int tid  = threadIdx.x;
    const int w    = tid >> 5, lane = tid & 31;
    const int wm   = w & 3, wn = w >> 2;       // rows 32*wm ; key-half/d-half 32|64*wn
    const int g    = lane >> 2, tib = lane & 3;
    const int b    = blockIdx.y, qt = blockIdx.x;

    // ---- prologue: K(0) async + Q fp32->fp16 direct ----
    loadTile64(sK0, g_Kh + (size_t)b * S * D, tid);
    CP_COMMIT();
    const size_t qoff = ((size_t)b * S + (size_t)qt * QT) * D;
    #pragma unroll
    for (int i = 0; i < 16; i++) {
        int idx = tid + i * THREADS;
        int row = idx >> 5, c4 = (idx & 31) * 4;
        float4 x = *(const float4*)(q + qoff + (size_t)row * D + c4);
        __half2 a = __floats2half2_rn(x.x, x.y);
        __half2 b2 = __floats2half2_rn(x.z, x.w);
        *(uint2*)(Qt + row * PADT + c4) = make_uint2(*(uint32_t*)&a, *(uint32_t*)&b2);
    }
    CP_WAIT(0);
    __syncthreads();

    // per-lane ldmatrix bases
    const uint32_t aQ0 = lmaddr(sQ, 32 * wm, 0, lane, PADT);
    const uint32_t aQ1 = lmaddr(sQ, 32 * wm + 16, 0, lane, PADT);
    const uint32_t aK0 = lmaddr(sK0, 32 * wn, 0, lane, PADT);
    const uint32_t aK1 = lmaddr(sK1, 32 * wn, 0, lane, PADT);
    const uint32_t aVB = lmaddrT(sV, 64 * wn, lane);
    const uint32_t aP0 = lmaddr(sP, 32 * wm, 0, lane, PADP);
    const uint32_t aP1 = lmaddr(sP, 32 * wm + 16, 0, lane, PADP);

    float O[2][8][4] = {};
    float Ls[4] = {0.f, 0.f, 0.f, 0.f};
    const float SC = 0.08838834764831843f;   // 1/sqrt(128)

    #pragma unroll 1
    for (int kt = 0; kt < NTILES; kt++) {
        // V(kt) prefetch (buffer free: prev PV done at trailing sync)
        loadTile64(sV, g_Vh + ((size_t)b * S + (size_t)kt * KT) * D, tid);
        CP_COMMIT();
        // K(kt+1) prefetch into other buffer
        if (kt + 1 < NTILES) {
            loadTile64((kt & 1) ? sK0 : sK1,
                       g_Kh + ((size_t)b * S + (size_t)(kt + 1) * KT) * D, tid);
            CP_COMMIT();
        }

        // ---- QK^T: warp computes rows 32wm..+31 x keys 32wn..+31 ----
        float Cr[2][4][4] = {};
        const uint32_t aK = (kt & 1) ? aK1 : aK0;
        #pragma unroll
        for (int kst = 0; kst < 8; kst++) {
            const uint32_t cofs = kst * 32u;
            uint32_t q0[4], q1[4];
            ldsm4(q0, aQ0 + cofs);
            ldsm4(q1, aQ1 + cofs);
            #pragma unroll
            for (int np = 0; np < 2; np++) {
                uint32_t k4[4];
                ldsm4(k4, aK + (uint32_t)(np * 16 * PADT) * 2u + cofs);
                mma16816(Cr[0][2 * np],     q0, k4[0], k4[2]);
                mma16816(Cr[0][2 * np + 1], q0, k4[1], k4[3]);
                mma16816(Cr[1][2 * np],     q1, k4[0], k4[2]);
                mma16816(Cr[1][2 * np + 1], q1, k4[1], k4[3]);
            }
        }

        // ---- exp, unnormalized attn out, P -> smem ----
        #pragma unroll
        for (int mt = 0; mt < 2; mt++) {
            const int lrow = 32 * wm + 16 * mt + g;
            float* arow = attn + ((size_t)(b * S + qt * QT + lrow)) * S
                        + kt * KT + 32 * wn + 2 * tib;
            #pragma unroll
            for (int n = 0; n < 4; n++) {
                float p0 = __expf(Cr[mt][n][0] * SC);
                float p1 = __expf(Cr[mt][n][1] * SC);
                float p2 = __expf(Cr[mt][n][2] * SC);
                float p3 = __expf(Cr[mt][n][3] * SC);
                Ls[2 * mt]     += p0 + p1;
                Ls[2 * mt + 1] += p2 + p3;
                *(float2*)(arow + 8 * n)                 = make_float2(p0, p1);
                *(float2*)(arow + 8 * (size_t)S + 8 * n) = make_float2(p2, p3);
                __half2 h0 = __floats2half2_rn(p0, p1);
                __half2 h1 = __floats2half2_rn(p2, p3);
                const int col = 32 * wn + 8 * n + 2 * tib;
                *(uint32_t*)(Ps + lrow * PADP + col)       = *(uint32_t*)&h0;
                *(uint32_t*)(Ps + (lrow + 8) * PADP + col) = *(uint32_t*)&h1;
            }
        }

        if (kt == NTILES - 1) { CP_WAIT(0); } else { CP_WAIT(1); }   // V(kt) landed
        __syncthreads();       // V + P visible

        // ---- PV: O += P * V ; warp: rows 32wm..+31 x d 64wn..+63 ----
        #pragma unroll
        for (int kst = 0; kst < 4; kst++) {
            const uint32_t cofs = kst * 32u;
            uint32_t a0[4], a1[4];
            ldsm4(a0, aP0 + cofs);
            ldsm4(a1, aP1 + cofs);
            #pragma unroll
            for (int np = 0; np < 4; np++) {
                uint32_t v4[4];
                ldsm4t(v4, aVB + (uint32_t)(16 * kst * PADT + 16 * np) * 2u);
                mma16816(O[0][2 * np],     a0, v4[0], v4[1]);
                mma16816(O[0][2 * np + 1], a0, v4[2], v4[3]);
                mma16816(O[1][2 * np],     a1, v4[0], v4[1]);
                mma16816(O[1][2 * np + 1], a1, v4[2], v4[3]);
            }
        }
        CP_WAIT(0);            // K(kt+1) landed
        __syncthreads();       // PV done: V,P buffers free; K visible
    }

    // ---- L reduction: quad shfl + cross-wn via smem (reuse P space) ----
    float* LR = (float*)Ps;
    #pragma unroll
    for (int i = 0; i < 4; i++) {
        float l = Ls[i];
        l += __shfl_xor_sync(0xffffffffu, l, 1);
        l += __shfl_xor_sync(0xffffffffu, l, 2);
        Ls[i] = l;
    }
    if (tib == 0) {
        #pragma unroll
        for (int mt = 0; mt < 2; mt++) {
            LR[wn * 128 + 32 * wm + 16 * mt + g]     = Ls[2 * mt];
            LR[wn * 128 + 32 * wm + 16 * mt + g + 8] = Ls[2 * mt + 1];
        }
    }
    __syncthreads();

    float inv[2][2];
    #pragma unroll
    for (int mt = 0; mt < 2; mt++) {
        int r0 = 32 * wm + 16 * mt + g;
        float L0 = LR[r0] + LR[128 + r0];
        float L1 = LR[r0 + 8] + LR[128 + r0 + 8];
        inv[mt][0] = 1.0f / L0;
        inv[mt][1] = 1.0f / L1;
        if (wn == 0 && tib == 0) {
            g_L[(size_t)b * S + qt * QT + r0]     = L0;
            g_L[(size_t)b * S + qt * QT + r0 + 8] = L1;
        }
    }

    // ---- normalized context store ----
    #pragma unroll
    for (int mt = 0; mt < 2; mt++) {
        const int lrow = 32 * wm + 16 * mt + g;
        float* cp = ctx + ((size_t)(b * S + qt * QT + lrow)) * D + 64 * wn + 2 * tib;
        #pragma unroll
        for (int n = 0; n < 8; n++) {
            *(float2*)(cp + 8 * n)         = make_float2(O[mt][n][0] * inv[mt][0],
                                                         O[mt][n][1] * inv[mt][0]);
            *(float2*)(cp + 8 * D + 8 * n) = make_float2(O[mt][n][2] * inv[mt][1],
                                                         O[mt][n][3] * inv[mt][1]);
        }
    }
}

// normalize attn in place: 8 float4 per thread, all one row (amortized g_L, MLP=8)
__global__ __launch_bounds__(256) void attn_norm_kernel(float* __restrict__ attn) {
    int idx = blockIdx.x * 256 + threadIdx.x;
    int row = idx >> 6;                      // 64 threads per row (512 float4/row)
    int c   = (idx & 63) * 8;
    float inv = 1.0f / g_L[row];
    float4* a = (float4*)(attn + (size_t)row * S) + c;
    #pragma unroll
    for (int j = 0; j < 8; j++) {
        float4 t = a[j];
        t.x *= inv; t.y *= inv; t.z *= inv; t.w *= inv;
        a[j] = t;
    }
}

// ---------------- launch ----------------
extern "C" void kernel_launch(void* const* d_in, const int* in_sizes, int n_in,
                              void* d_out, int out_size) {
    const float* q = (const float*)d_in[0];
    const float* k = (const float*)d_in[1];
    const float* v = (const float*)d_in[2];
    float* ctx  = (float*)d_out;                       // [B,S,D]
    float* attn = (float*)d_out + (size_t)B * S * D;   // [B,S,S]

    cudaFuncSetAttribute(attn_mma_kernel,
                         cudaFuncAttributeMaxDynamicSharedMemorySize, SMEM_TOTAL);

    prep_kernel<<<dim3((B * S * D / 4) / 256, 2), 256>>>(k, v);
    attn_mma_kernel<<<dim3(S / QT, B), THREADS, SMEM_TOTAL>>>(q, ctx, attn);
    attn_norm_kernel<<<(B * S * 64) / 256, 256>>>(attn);
}

// round 10
// speedup vs baseline: 1.2934x; 1.1293x over previous
#include <cuda_runtime.h>
#include <cuda_fp16.h>
#include <cstdint>

#define B 16
#define S 2048
#define D 128
#define QT 128
#define KT 64
#define NTILES (S / KT)          // 32
#define THREADS 256
#define PADT 136                 // stride (fp16) for 128-col tiles -> conflict-free LDSM
#define PADP 72                  // stride (fp16) for 64-col P tile -> conflict-free LDSM
#define TBQ (128 * PADT * 2)     // 34816 B  (Q tile)
#define TBK (KT * PADT * 2)      // 17408 B  (K / V tiles)
#define TBP (128 * PADP * 2)     // 18432 B  (P tile)
#define SMEM_TOTAL (TBQ + 3 * TBK + TBP)   // 105472 B -> 2 CTAs/SM

// ---------------- device scratch (no allocation allowed) ----------------
__device__ __half g_Kh[B * S * D];
__device__ __half g_Vh[B * S * D];
__device__ __half g_P[(size_t)B * S * S];   // unnormalized attn, fp16 (134 MB)
__device__ float g_L[B * S];

// ---------------- PTX helpers (baseline sm_80-level features only) ----------------
__device__ __forceinline__ uint32_t smem_u32(const void* p) {
    uint32_t a;
    asm("{ .reg .u64 t; cvta.to.shared.u64 t, %1; cvt.u32.u64 %0, t; }" : "=r"(a) : "l"(p));
    return a;
}
__device__ __forceinline__ void ldsm4(uint32_t r[4], uint32_t a) {
    asm volatile("ldmatrix.sync.aligned.m8n8.x4.shared.b16 {%0,%1,%2,%3}, [%4];"
                 : "=r"(r[0]), "=r"(r[1]), "=r"(r[2]), "=r"(r[3]) : "r"(a));
}
__device__ __forceinline__ void ldsm4t(uint32_t r[4], uint32_t a) {
    asm volatile("ldmatrix.sync.aligned.m8n8.x4.trans.shared.b16 {%0,%1,%2,%3}, [%4];"
                 : "=r"(r[0]), "=r"(r[1]), "=r"(r[2]), "=r"(r[3]) : "r"(a));
}
__device__ __forceinline__ void mma16816(float c[4], const uint32_t a[4],
                                         uint32_t b0, uint32_t b1) {
    asm("mma.sync.aligned.m16n8k16.row.col.f32.f16.f16.f32 "
        "{%0,%1,%2,%3},{%4,%5,%6,%7},{%8,%9},{%0,%1,%2,%3};"
        : "+f"(c[0]), "+f"(c[1]), "+f"(c[2]), "+f"(c[3])
        : "r"(a[0]), "r"(a[1]), "r"(a[2]), "r"(a[3]), "r"(b0), "r"(b1));
}
__device__ __forceinline__ float ex2(float x) {
    float r;
    asm("ex2.approx.ftz.f32 %0, %1;" : "=f"(r) : "f"(x));
    return r;
}
__device__ __forceinline__ void cp16(uint32_t s, const void* g) {
    asm volatile("cp.async.cg.shared.global [%0], [%1], 16;" :: "r"(s), "l"(g) : "memory");
}
#define CP_COMMIT()  asm volatile("cp.async.commit_group;" ::: "memory")
#define CP_WAIT(n)   asm volatile("cp.async.wait_group %0;" :: "n"(n) : "memory")

// per-lane ldmatrix.x4 base (non-trans) at (row0,col0), given row stride in elems
__device__ __forceinline__ uint32_t lmaddr(uint32_t base, int row0, int col0,
                                           int lane, int stride) {
    int r = lane & 7, which = lane >> 3;
    int row = row0 + ((which & 1) << 3) + r;
    int col = col0 + ((which >> 1) << 3);
    return base + (uint32_t)(row * stride + col) * 2u;
}
// per-lane ldmatrix.x4.trans base for V[s][d] tiles (stride PADT)
__device__ __forceinline__ uint32_t lmaddrT(uint32_t base, int col0, int lane) {
    int row = (lane & 7) + 8 * ((lane >> 3) & 1);    // key offset
    int col = col0 + 8 * (lane >> 4);                // d offset
    return base + (uint32_t)(row * PADT + col) * 2u;
}

// cooperative async 64x128 fp16 tile copy: gmem(D stride) -> padded smem
__device__ __forceinline__ void loadTile64(uint32_t sdst, const __half* __restrict__ src,
                                           int tid) {
    #pragma unroll
    for (int i = 0; i < 4; i++) {
        int idx = tid + i * THREADS;       // 1024 16B chunks
        int row = idx >> 4;
        int c   = (idx & 15) * 8;
        cp16(sdst + (uint32_t)(row * PADT + c) * 2u, src + (size_t)row * D + c);
    }
}

// ---------------- pre-kernel: K,V -> fp16 ----------------
__global__ __launch_bounds__(256) void prep_kernel(const float* __restrict__ k,
                                                   const float* __restrict__ v) {
    size_t i = ((size_t)blockIdx.x * 256 + threadIdx.x) * 4;
    const float* src = (blockIdx.y == 0) ? k : v;
    __half* dst = (blockIdx.y == 0) ? g_Kh : g_Vh;
    float4 x = *(const float4*)(src + i);
    __half2 a = __floats2half2_rn(x.x, x.y);
    __half2 b2 = __floats2half2_rn(x.z, x.w);
    *(uint2*)(dst + i) = make_uint2(*(uint32_t*)&a, *(uint32_t*)&b2);
}

// ---------------- main attention kernel ----------------
// smem: [Q:0][K0:TBQ][K1:+TBK][V:+TBK][P:+TBK]
__global__ __launch_bounds__(THREADS, 2) void attn_mma_kernel(const float* __restrict__ q,
                                                              float* __restrict__ ctx) {
    extern __shared__ char smraw[];
    uint32_t sb = smem_u32(smraw);
    const uint32_t sQ = sb, sK0 = sb + TBQ, sK1 = sK0 + TBK;
    const uint32_t sV = sK1 + TBK, sP = sV + TBK;
    __half* Qt = (__half*)smraw;
    __half* Ps = (__half*)(smraw + TBQ + 3 * TBK);

    const int tid  = threadIdx.x;
    const int w    = tid >> 5, lane = tid & 31;
    const int wm   = w & 3, wn = w >> 2;       // rows 32*wm ; key-half/d-half 32|64*wn
    const int g    = lane >> 2, tib = lane & 3;
    const int b    = blockIdx.y, qt = blockIdx.x;

    // ---- prologue: K(0) async + Q fp32->fp16 direct ----
    loadTile64(sK0, g_Kh + (size_t)b * S * D, tid);
    CP_COMMIT();
    const size_t qoff = ((size_t)b * S + (size_t)qt * QT) * D;
    #pragma unroll
    for (int i = 0; i < 16; i++) {
        int idx = tid + i * THREADS;
        int row = idx >> 5, c4 = (idx & 31) * 4;
        float4 x = *(const float4*)(q + qoff + (size_t)row * D + c4);
        __half2 a = __floats2half2_rn(x.x, x.y);
        __half2 b2 = __floats2half2_rn(x.z, x.w);
        *(uint2*)(Qt + row * PADT + c4) = make_uint2(*(uint32_t*)&a, *(uint32_t*)&b2);
    }
    CP_WAIT(0);
    __syncthreads();

    // per-lane ldmatrix bases
    const uint32_t aQ0 = lmaddr(sQ, 32 * wm, 0, lane, PADT);
    const uint32_t aQ1 = lmaddr(sQ, 32 * wm + 16, 0, lane, PADT);
    const uint32_t aK0 = lmaddr(sK0, 32 * wn, 0, lane, PADT);
    const uint32_t aK1 = lmaddr(sK1, 32 * wn, 0, lane, PADT);
    const uint32_t aVB = lmaddrT(sV, 64 * wn, lane);
    const uint32_t aP0 = lmaddr(sP, 32 * wm, 0, lane, PADP);
    const uint32_t aP1 = lmaddr(sP, 32 * wm + 16, 0, lane, PADP);

    float O[2][8][4] = {};
    float Ls[4] = {0.f, 0.f, 0.f, 0.f};
    const float SC2 = 0.12755102624059892f;  // 1/sqrt(128) * log2(e)

    #pragma unroll 1
    for (int kt = 0; kt < NTILES; kt++) {
        // V(kt) prefetch (buffer free: prev PV done at trailing sync)
        loadTile64(sV, g_Vh + ((size_t)b * S + (size_t)kt * KT) * D, tid);
        CP_COMMIT();
        // K(kt+1) prefetch into other buffer
        if (kt + 1 < NTILES) {
            loadTile64((kt & 1) ? sK0 : sK1,
                       g_Kh + ((size_t)b * S + (size_t)(kt + 1) * KT) * D, tid);
            CP_COMMIT();
        }

        // ---- QK^T: warp computes rows 32wm..+31 x keys 32wn..+31 ----
        float Cr[2][4][4] = {};
        const uint32_t aK = (kt & 1) ? aK1 : aK0;
        #pragma unroll
        for (int kst = 0; kst < 8; kst++) {
            const uint32_t cofs = kst * 32u;
            uint32_t q0[4], q1[4];
            ldsm4(q0, aQ0 + cofs);
            ldsm4(q1, aQ1 + cofs);
            #pragma unroll
            for (int np = 0; np < 2; np++) {
                uint32_t k4[4];
                ldsm4(k4, aK + (uint32_t)(np * 16 * PADT) * 2u + cofs);
                mma16816(Cr[0][2 * np],     q0, k4[0], k4[2]);
                mma16816(Cr[0][2 * np + 1], q0, k4[1], k4[3]);
                mma16816(Cr[1][2 * np],     q1, k4[0], k4[2]);
                mma16816(Cr[1][2 * np + 1], q1, k4[1], k4[3]);
            }
        }

        // ---- exp, fp16 scratch out, P -> smem ----
        #pragma unroll
        for (int mt = 0; mt < 2; mt++) {
            const int lrow = 32 * wm + 16 * mt + g;
            __half* prow = g_P + ((size_t)(b * S + qt * QT + lrow)) * S
                         + kt * KT + 32 * wn + 2 * tib;
            #pragma unroll
            for (int n = 0; n < 4; n++) {
                float p0 = ex2(Cr[mt][n][0] * SC2);
                float p1 = ex2(Cr[mt][n][1] * SC2);
                float p2 = ex2(Cr[mt][n][2] * SC2);
                float p3 = ex2(Cr[mt][n][3] * SC2);
                Ls[2 * mt]     += p0 + p1;
                Ls[2 * mt + 1] += p2 + p3;
                __half2 h0 = __floats2half2_rn(p0, p1);
                __half2 h1 = __floats2half2_rn(p2, p3);
                uint32_t u0 = *(uint32_t*)&h0, u1 = *(uint32_t*)&h1;
                *(uint32_t*)(prow + 8 * n)               = u0;  // row lrow
                *(uint32_t*)(prow + 8 * (size_t)S + 8 * n) = u1; // row lrow+8
                const int col = 32 * wn + 8 * n + 2 * tib;
                *(uint32_t*)(Ps + lrow * PADP + col)       = u0;
                *(uint32_t*)(Ps + (lrow + 8) * PADP + col) = u1;
            }
        }

        if (kt == NTILES - 1) { CP_WAIT(0); } else { CP_WAIT(1); }   // V(kt) landed
        __syncthreads();       // V + P visible

        // ---- PV: O += P * V ; warp: rows 32wm..+31 x d 64wn..+63 ----
        #pragma unroll
        for (int kst = 0; kst < 4; kst++) {
            const uint32_t cofs = kst * 32u;
            uint32_t a0[4], a1[4];
            ldsm4(a0, aP0 + cofs);
            ldsm4(a1, aP1 + cofs);
            #pragma unroll
            for (int np = 0; np < 4; np++) {
                uint32_t v4[4];
                ldsm4t(v4, aVB + (uint32_t)(16 * kst * PADT + 16 * np) * 2u);
                mma16816(O[0][2 * np],     a0, v4[0], v4[1]);
                mma16816(O[0][2 * np + 1], a0, v4[2], v4[3]);
                mma16816(O[1][2 * np],     a1, v4[0], v4[1]);
                mma16816(O[1][2 * np + 1], a1, v4[2], v4[3]);
            }
        }
        CP_WAIT(0);            // K(kt+1) landed
        __syncthreads();       // PV done: V,P buffers free; K visible
    }

    // ---- L reduction: quad shfl + cross-wn via smem (reuse P space) ----
    float* LR = (float*)Ps;
    #pragma unroll
    for (int i = 0; i < 4; i++) {
        float l = Ls[i];
        l += __shfl_xor_sync(0xffffffffu, l, 1);
        l += __shfl_xor_sync(0xffffffffu, l, 2);
        Ls[i] = l;
    }
    if (tib == 0) {
        #pragma unroll
        for (int mt = 0; mt < 2; mt++) {
            LR[wn * 128 + 32 * wm + 16 * mt + g]     = Ls[2 * mt];
            LR[wn * 128 + 32 * wm + 16 * mt + g + 8] = Ls[2 * mt + 1];
        }
    }
    __syncthreads();

    float inv[2][2];
    #pragma unroll
    for (int mt = 0; mt < 2; mt++) {
        int r0 = 32 * wm + 16 * mt + g;
        float L0 = LR[r0] + LR[128 + r0];
        float L1 = LR[r0 + 8] + LR[128 + r0 + 8];
        inv[mt][0] = 1.0f / L0;
        inv[mt][1] = 1.0f / L1;
        if (wn == 0 && tib == 0) {
            g_L[(size_t)b * S + qt * QT + r0]     = L0;
            g_L[(size_t)b * S + qt * QT + r0 + 8] = L1;
        }
    }

    // ---- normalized context store ----
    #pragma unroll
    for (int mt = 0; mt < 2; mt++) {
        const int lrow = 32 * wm + 16 * mt + g;
        float* cp = ctx + ((size_t)(b * S + qt * QT + lrow)) * D + 64 * wn + 2 * tib;
        #pragma unroll
        for (int n = 0; n < 8; n++) {
            *(float2*)(cp + 8 * n)         = make_float2(O[mt][n][0] * inv[mt][0],
                                                         O[mt][n][1] * inv[mt][0]);
            *(float2*)(cp + 8 * D + 8 * n) = make_float2(O[mt][n][2] * inv[mt][1],
                                                         O[mt][n][3] * inv[mt][1]);
        }
    }
}

// normalize: attn[row][c] = fp32(g_P[row][c]) / L[row]
__global__ __launch_bounds__(256) void attn_norm_kernel(float* __restrict__ attn) {
    int idx = blockIdx.x * 256 + threadIdx.x;
    int row = idx >> 6;                      // 64 threads per row
    int c   = (idx & 63) * 32;               // 32 halves per thread
    float inv = 1.0f / g_L[row];
    const __half2* p = (const __half2*)(g_P + (size_t)row * S + c);
    float4* a = (float4*)(attn + (size_t)row * S + c);
    #pragma unroll
    for (int j = 0; j < 8; j++) {
        float2 f0 = __half22float2(p[2 * j]);
        float2 f1 = __half22float2(p[2 * j + 1]);
        a[j] = make_float4(f0.x * inv, f0.y * inv, f1.x * inv, f1.y * inv);
    }
}

// ---------------- launch ----------------
extern "C" void kernel_launch(void* const* d_in, const int* in_sizes, int n_in,
                              void* d_out, int out_size) {
    const float* q = (const float*)d_in[0];
    const float* k = (const float*)d_in[1];
    const float* v = (const float*)d_in[2];
    float* ctx  = (float*)d_out;                       // [B,S,D]
    float* attn = (float*)d_out + (size_t)B * S * D;   // [B,S,S]

    cudaFuncSetAttribute(attn_mma_kernel,
                         cudaFuncAttributeMaxDynamicSharedMemorySize, SMEM_TOTAL);

    prep_kernel<<<dim3((B * S * D / 4) / 256, 2), 256>>>(k, v);
    attn_mma_kernel<<<dim3(S / QT, B), THREADS, SMEM_TOTAL>>>(q, ctx);
    attn_norm_kernel<<<(B * S * 64) / 256, 256>>>(attn);
}